// round 11
// baseline (speedup 1.0000x reference)
#include <cuda_runtime.h>

// Problem constants
#define Bn   2
#define Cc   64
#define Oo   64
#define Gg   16
#define Ee   128
#define Tin  512
#define Wk   7
#define Dd   4
#define Tout 256
#define FO   64
#define PER  264   // padded de-interleaved row length (floats)

// Per-warp BN-stat partials: [o][slot], slot = b*128 + (c&3)*32 + fq (256)
__device__ float  g_part1[Oo][256];
__device__ float  g_part2[Oo][256];
__device__ float2 g_ab[Oo];           // {a, bias56}

// ---------------------------------------------------------------------------
// Merged kernel: 2048 blocks x 192 threads, warp-specialized.
//   warps 0-3 (tid 0..127): conv tile (b,g,fo) -> RAW pooled accumulator.
//     Synchronize among themselves via named barrier 1 (128 threads).
//   warps 4-5: stats warps. sw = bid*2 + (warp-4) in [0,4096); each warp
//     covers 4 x-rows via 8-lane groups; writes per-warp partials (no atomics).
// ---------------------------------------------------------------------------
__global__ __launch_bounds__(192) void merged_kernel(const float* __restrict__ x,
                                                     const float* __restrict__ wgt,
                                                     float* __restrict__ out) {
    __shared__ alignas(16) float pe[8][PER];
    __shared__ alignas(16) float pos_[8][PER];
    __shared__ alignas(16) float ws[8][4][8];   // [w0..w6, 0]

    const int bid  = blockIdx.x;
    const int tid  = threadIdx.x;
    const int lane = tid & 31;
    const int warp = tid >> 5;

    if (warp >= 4) {
        // ===================== STATS PATH (warps 4,5) =====================
        const int sw   = bid * 2 + (warp - 4);     // 0..4095
        const int b    = sw >> 11;
        const int c    = (sw >> 5) & 63;
        const int fq   = sw & 31;
        const int sl   = lane & 7;
        const int gidx = lane >> 3;
        const int f    = fq * 4 + gidx;

        const float4* row = reinterpret_cast<const float4*>(
            &x[((b * Cc + c) * Ee + f) * Tin]);

        float se = 0.f, so = 0.f, se2 = 0.f, so2 = 0.f;
        float4 vfirst, vlast;
        {
            float4 v[8];
#pragma unroll
            for (int k = 0; k < 8; k++) v[k] = row[sl + 8 * k];
            vfirst = v[0];
#pragma unroll
            for (int k = 0; k < 8; k++) {
                float4 q = v[k];
                se += q.x + q.z;  so += q.y + q.w;
                se2 = fmaf(q.x, q.x, se2); se2 = fmaf(q.z, q.z, se2);
                so2 = fmaf(q.y, q.y, so2); so2 = fmaf(q.w, q.w, so2);
            }
        }
        {
            float4 v[8];
#pragma unroll
            for (int k = 0; k < 8; k++) v[k] = row[sl + 8 * (k + 8)];
            vlast = v[7];
#pragma unroll
            for (int k = 0; k < 8; k++) {
                float4 q = v[k];
                se += q.x + q.z;  so += q.y + q.w;
                se2 = fmaf(q.x, q.x, se2); se2 = fmaf(q.z, q.z, se2);
                so2 = fmaf(q.y, q.y, so2); so2 = fmaf(q.w, q.w, so2);
            }
        }

        const unsigned FULL = 0xffffffffu;
        const int base = lane & ~7;
        float x0   = __shfl_sync(FULL, vfirst.x, base);
        float x1   = __shfl_sync(FULL, vfirst.y, base);
        float x509 = __shfl_sync(FULL, vlast.y,  base + 7);
        float x510 = __shfl_sync(FULL, vlast.z,  base + 7);
        float x511 = __shfl_sync(FULL, vlast.w,  base + 7);

#pragma unroll
        for (int off = 1; off < 8; off <<= 1) {
            se  += __shfl_xor_sync(FULL, se,  off);
            so  += __shfl_xor_sync(FULL, so,  off);
            se2 += __shfl_xor_sync(FULL, se2, off);
            so2 += __shfl_xor_sync(FULL, so2, off);
        }

        float c1 = 0.f, c2 = 0.f;
        if (sl < 4) {
            float s1[7], s2[7];
            s1[0] = so - x509 - x511;  s2[0] = so2 - x509 * x509 - x511 * x511;
            s1[1] = se - x510;         s2[1] = se2 - x510 * x510;
            s1[2] = so - x511;         s2[2] = so2 - x511 * x511;
            s1[3] = se;                s2[3] = se2;
            s1[4] = so;                s2[4] = so2;
            s1[5] = se - x0;           s2[5] = se2 - x0 * x0;
            s1[6] = so - x1;           s2[6] = so2 - x1 * x1;

            const int g = c >> 2, d = c & 3;
            const int o = g * 4 + sl;
            const float* wp = &wgt[((o * Dd + d) * Ee + f) * Wk];
#pragma unroll
            for (int w = 0; w < 7; w++) {
                float wv = wp[w];
                c1 = fmaf(wv, s1[w], c1);
                c2 = fmaf(wv * wv, s2[w], c2);
            }
        }
        // fold the 4 groups (rows) of the warp
        c1 += __shfl_xor_sync(FULL, c1, 8);
        c1 += __shfl_xor_sync(FULL, c1, 16);
        c2 += __shfl_xor_sync(FULL, c2, 8);
        c2 += __shfl_xor_sync(FULL, c2, 16);
        if (lane < 4) {
            const int g = c >> 2;
            const int slot = b * 128 + (c & 3) * 32 + fq;
            g_part1[g * 4 + lane][slot] = c1;
            g_part2[g * 4 + lane][slot] = c2;
        }
        return;
    }

    // ===================== CONV PATH (warps 0-3) =====================
    const int b   = bid >> 10;
    const int g   = (bid >> 6) & 15;
    const int fo  = bid & 63;
    const int oc  = lane & 3;
    const int tc  = warp * 8 + (lane >> 2);  // 0..31; outputs t = 8tc..8tc+7

    // zero boundary slots {0,1,258..263} of each pe/pos_ row (tid 0..127)
    {
        int r  = tid >> 4;
        int s  = tid & 15;
        int ss = s & 7;
        int idx = (ss < 2) ? ss : (256 + ss);
        if (s < 8) pe[r][idx] = 0.f; else pos_[r][idx] = 0.f;
    }

    // de-interleaving fill
#pragma unroll
    for (int k = 0; k < 8; k++) {
        const int c = g * 4 + (k & 3);
        const int f = 2 * fo + (k >> 2);
        float4 v = reinterpret_cast<const float4*>(
            &x[((b * Cc + c) * Ee + f) * Tin])[tid];
        *reinterpret_cast<float2*>(&pe[k][2 * tid + 2])   = make_float2(v.y, v.w);
        *reinterpret_cast<float2*>(&pos_[k][2 * tid + 2]) = make_float2(v.x, v.z);
    }

    // weights
#pragma unroll
    for (int m = 0; m < 2; m++) {
        int j  = tid + 128 * m;
        int r  = j >> 5;
        int o2 = (j >> 3) & 3;
        int w  = j & 7;
        int d  = r & 3;
        int f2 = r >> 2;
        ws[r][o2][w] = (w < 7)
            ? wgt[(((g * 4 + o2) * Dd + d) * Ee + (2 * fo + f2)) * Wk + w] : 0.f;
    }
    // named barrier: only the 4 conv warps (128 threads)
    asm volatile("bar.sync 1, 128;" ::: "memory");

    float acc[8];
#pragma unroll
    for (int j = 0; j < 8; j++) acc[j] = 0.f;

#pragma unroll
    for (int r = 0; r < 8; r++) {
        const float4* pe4  = reinterpret_cast<const float4*>(pe[r]);
        const float4* pos4 = reinterpret_cast<const float4*>(pos_[r]);
        float E[12], S[12];
        *reinterpret_cast<float4*>(&E[0]) = pe4[2 * tc];
        *reinterpret_cast<float4*>(&E[4]) = pe4[2 * tc + 1];
        *reinterpret_cast<float4*>(&E[8]) = pe4[2 * tc + 2];
        *reinterpret_cast<float4*>(&S[0]) = pos4[2 * tc];
        *reinterpret_cast<float4*>(&S[4]) = pos4[2 * tc + 1];
        *reinterpret_cast<float4*>(&S[8]) = pos4[2 * tc + 2];
        float4 wA = *reinterpret_cast<const float4*>(&ws[r][oc][0]);
        float4 wB = *reinterpret_cast<const float4*>(&ws[r][oc][4]);
#pragma unroll
        for (int j = 0; j < 8; j++) {
            acc[j] = fmaf(wA.x, E[j],     acc[j]);
            acc[j] = fmaf(wA.y, S[j + 1], acc[j]);
            acc[j] = fmaf(wA.z, E[j + 1], acc[j]);
            acc[j] = fmaf(wA.w, S[j + 2], acc[j]);
            acc[j] = fmaf(wB.x, E[j + 2], acc[j]);
            acc[j] = fmaf(wB.y, S[j + 3], acc[j]);
            acc[j] = fmaf(wB.z, E[j + 3], acc[j]);
        }
    }

    {
        int ob = ((b * Oo + g * 4 + oc) * FO + fo) * Tout + 8 * tc;
        *reinterpret_cast<float4*>(&out[ob])     = make_float4(acc[0], acc[1], acc[2], acc[3]);
        *reinterpret_cast<float4*>(&out[ob + 4]) = make_float4(acc[4], acc[5], acc[6], acc[7]);
    }
}

// ---------------------------------------------------------------------------
// Finalize: 1 block, 256 threads. Thread (o = tid>>2, q = tid&3) sums 64 of
// the 256 partials (16 float4), 2-level shfl fold, q==0 writes g_ab.
// ---------------------------------------------------------------------------
__global__ __launch_bounds__(256) void finalize_kernel(const float* __restrict__ gamma,
                                                       const float* __restrict__ beta) {
    const int tid = threadIdx.x;
    const int o = tid >> 2, q = tid & 3;
    const float4* p1v = reinterpret_cast<const float4*>(&g_part1[o][q * 64]);
    const float4* p2v = reinterpret_cast<const float4*>(&g_part2[o][q * 64]);
    float p1 = 0.f, p2 = 0.f;
#pragma unroll
    for (int k = 0; k < 16; k++) {
        float4 a = p1v[k], b = p2v[k];
        p1 += (a.x + a.y) + (a.z + a.w);
        p2 += (b.x + b.y) + (b.z + b.w);
    }
#pragma unroll
    for (int off = 1; off < 4; off <<= 1) {
        p1 += __shfl_xor_sync(0xffffffffu, p1, off);
        p2 += __shfl_xor_sync(0xffffffffu, p2, off);
    }
    if (q == 0) {
        const float M = 1835008.f;   // B*D*E*t*W
        float mean = p1 / M;
        float var  = p2 / M - mean * mean;
        float a    = gamma[o] * rsqrtf(var + 1e-5f);
        g_ab[o] = make_float2(a, 56.f * (beta[o] - mean * a));
    }
}

// ---------------------------------------------------------------------------
// Apply: in-place affine + LeakyReLU on out (L2-warm). Max TLP: 2048 blocks
// x 256 threads x 1 float4 RMW (524288 float4 total).
// ---------------------------------------------------------------------------
__global__ __launch_bounds__(256) void apply_kernel(float* __restrict__ out) {
    const int idx = blockIdx.x * 256 + threadIdx.x;   // float4 index
    const int o   = (idx >> 12) & 63;                 // 4096 float4 per (b,o)
    const float2 ab = g_ab[o];
    float4* o4 = reinterpret_cast<float4*>(out);
    float4 v = o4[idx];
    float4 r;
    r.x = fmaf(ab.x, v.x, ab.y);
    r.y = fmaf(ab.x, v.y, ab.y);
    r.z = fmaf(ab.x, v.z, ab.y);
    r.w = fmaf(ab.x, v.w, ab.y);
    r.x = (r.x >= 0.f) ? r.x : 0.01f * r.x;
    r.y = (r.y >= 0.f) ? r.y : 0.01f * r.y;
    r.z = (r.z >= 0.f) ? r.z : 0.01f * r.z;
    r.w = (r.w >= 0.f) ? r.w : 0.01f * r.w;
    o4[idx] = r;
}

extern "C" void kernel_launch(void* const* d_in, const int* in_sizes, int n_in,
                              void* d_out, int out_size) {
    const float* x     = (const float*)d_in[0];
    const float* wgt   = (const float*)d_in[1];
    const float* gamma = (const float*)d_in[2];
    const float* beta  = (const float*)d_in[3];

    merged_kernel<<<2048, 192>>>(x, wgt, (float*)d_out);
    finalize_kernel<<<1, 256>>>(gamma, beta);
    apply_kernel<<<2048, 256>>>((float*)d_out);
}

// round 12
// speedup vs baseline: 1.1825x; 1.1825x over previous
#include <cuda_runtime.h>

// Problem constants
#define Bn   2
#define Cc   64
#define Oo   64
#define Gg   16
#define Ee   128
#define Tin  512
#define Wk   7
#define Dd   4
#define Tout 256
#define FO   64
#define PER  264   // padded de-interleaved row length (floats)
#define NBLK 1024

// BN-stat partials: [o][slot], slot = b*32 + fp  (64 slots per channel)
__device__ float    g_part1[Oo][64];
__device__ float    g_part2[Oo][64];
__device__ unsigned g_count;   // zero-initialized at module load
__device__ unsigned g_epoch;   // versioned barrier (graph-replay safe)

// ---------------------------------------------------------------------------
// Single persistent kernel. Block = (b, g, fp), 1024 blocks, 128 threads,
// 8 blocks/SM forced -> all 1024 co-resident (148 SMs * 8 = 1184 slots).
//   Phase 1: two conv tiles (fo = 2fp, 2fp+1), acc kept in registers.
//            S2 partials from x^2 sums accumulated during the smem fill;
//            S1 partials from the raw conv accumulators (free).
//   Grid barrier (epoch-versioned atomic counter).
//   Phase 2: per-block reduce of this group's 4 channels -> a/bias.
//   Phase 3: affine + LeakyReLU applied from registers, single final store.
// ---------------------------------------------------------------------------
__global__ __launch_bounds__(128, 8) void fused_kernel(const float* __restrict__ x,
                                                       const float* __restrict__ wgt,
                                                       const float* __restrict__ gamma,
                                                       const float* __restrict__ beta,
                                                       float* __restrict__ out) {
    __shared__ alignas(16) float pe[8][PER];
    __shared__ alignas(16) float pos_[8][PER];
    __shared__ alignas(16) float ws[8][4][8];   // [w0..w6, 0]
    __shared__ float  s_p1[4], s_p2[4];
    __shared__ float2 s_ab[4];

    const int bid  = blockIdx.x;
    const int b    = bid >> 9;
    const int g    = (bid >> 5) & 15;
    const int fp   = bid & 31;
    const int tid  = threadIdx.x;
    const int lane = tid & 31;
    const int warp = tid >> 5;
    const int oc   = lane & 3;
    const int tc   = warp * 8 + (lane >> 2);   // 0..31
    const int rf   = tid >> 4;                 // fill row 0..7
    const int j16  = tid & 15;

    const unsigned epoch  = g_epoch;           // read before any barrier work
    const unsigned target = (epoch + 1u) * NBLK;

    if (tid < 4) { s_p1[tid] = 0.f; s_p2[tid] = 0.f; }

    // zero boundary slots {0,1,258..263} of each pe/pos_ row (persist: never
    // overwritten by fills, which write indices 2..257 only)
    {
        int r  = tid >> 4;
        int s  = tid & 15;
        int ss = s & 7;
        int idx = (ss < 2) ? ss : (256 + ss);
        if (s < 8) pe[r][idx] = 0.f; else pos_[r][idx] = 0.f;
    }

    float acc[2][8];
    const unsigned FULL = 0xffffffffu;

#pragma unroll
    for (int m = 0; m < 2; m++) {
        const int fo = 2 * fp + m;

        // ---- fill row rf (8 float4) + in-register x^2 parity sums ----
        float se2 = 0.f, so2 = 0.f;   // even-index / odd-index sums of x^2
        {
            const int cf = g * 4 + (rf & 3);
            const int ff = 2 * fo + (rf >> 2);
            const float4* xrow = reinterpret_cast<const float4*>(
                &x[((b * Cc + cf) * Ee + ff) * Tin]);
#pragma unroll
            for (int k = 0; k < 8; k++) {
                int i = j16 + 16 * k;
                float4 v = xrow[i];
                *reinterpret_cast<float2*>(&pe[rf][2 * i + 2])   = make_float2(v.y, v.w);
                *reinterpret_cast<float2*>(&pos_[rf][2 * i + 2]) = make_float2(v.x, v.z);
                se2 = fmaf(v.x, v.x, se2); se2 = fmaf(v.z, v.z, se2);
                so2 = fmaf(v.y, v.y, so2); so2 = fmaf(v.w, v.w, so2);
            }
        }
        // weights for this tile
#pragma unroll
        for (int mm = 0; mm < 2; mm++) {
            int j  = tid + 128 * mm;
            int r  = j >> 5;
            int o2 = (j >> 3) & 3;
            int w  = j & 7;
            int d  = r & 3;
            int f2 = r >> 2;
            ws[r][o2][w] = (w < 7)
                ? wgt[(((g * 4 + o2) * Dd + d) * Ee + (2 * fo + f2)) * Wk + w] : 0.f;
        }
        __syncthreads();

        // ---- conv: 8 outputs per thread (validated core) ----
        float a0 = 0.f, a1 = 0.f, a2 = 0.f, a3 = 0.f;
        float a4 = 0.f, a5 = 0.f, a6 = 0.f, a7 = 0.f;
#pragma unroll
        for (int r = 0; r < 8; r++) {
            const float4* pe4  = reinterpret_cast<const float4*>(pe[r]);
            const float4* pos4 = reinterpret_cast<const float4*>(pos_[r]);
            float E[12], S[12];
            *reinterpret_cast<float4*>(&E[0]) = pe4[2 * tc];
            *reinterpret_cast<float4*>(&E[4]) = pe4[2 * tc + 1];
            *reinterpret_cast<float4*>(&E[8]) = pe4[2 * tc + 2];
            *reinterpret_cast<float4*>(&S[0]) = pos4[2 * tc];
            *reinterpret_cast<float4*>(&S[4]) = pos4[2 * tc + 1];
            *reinterpret_cast<float4*>(&S[8]) = pos4[2 * tc + 2];
            float4 wA = *reinterpret_cast<const float4*>(&ws[r][oc][0]);
            float4 wB = *reinterpret_cast<const float4*>(&ws[r][oc][4]);
            float t0, t1, t2, t3, t4, t5, t6, t7;
            t0 = fmaf(wA.x, E[0], fmaf(wA.y, S[1], fmaf(wA.z, E[1], 0.f)));
            t1 = fmaf(wA.x, E[1], fmaf(wA.y, S[2], fmaf(wA.z, E[2], 0.f)));
            t2 = fmaf(wA.x, E[2], fmaf(wA.y, S[3], fmaf(wA.z, E[3], 0.f)));
            t3 = fmaf(wA.x, E[3], fmaf(wA.y, S[4], fmaf(wA.z, E[4], 0.f)));
            t4 = fmaf(wA.x, E[4], fmaf(wA.y, S[5], fmaf(wA.z, E[5], 0.f)));
            t5 = fmaf(wA.x, E[5], fmaf(wA.y, S[6], fmaf(wA.z, E[6], 0.f)));
            t6 = fmaf(wA.x, E[6], fmaf(wA.y, S[7], fmaf(wA.z, E[7], 0.f)));
            t7 = fmaf(wA.x, E[7], fmaf(wA.y, S[8], fmaf(wA.z, E[8], 0.f)));
            t0 = fmaf(wA.w, S[2], fmaf(wB.x, E[2], fmaf(wB.y, S[3], fmaf(wB.z, E[3], t0))));
            t1 = fmaf(wA.w, S[3], fmaf(wB.x, E[3], fmaf(wB.y, S[4], fmaf(wB.z, E[4], t1))));
            t2 = fmaf(wA.w, S[4], fmaf(wB.x, E[4], fmaf(wB.y, S[5], fmaf(wB.z, E[5], t2))));
            t3 = fmaf(wA.w, S[5], fmaf(wB.x, E[5], fmaf(wB.y, S[6], fmaf(wB.z, E[6], t3))));
            t4 = fmaf(wA.w, S[6], fmaf(wB.x, E[6], fmaf(wB.y, S[7], fmaf(wB.z, E[7], t4))));
            t5 = fmaf(wA.w, S[7], fmaf(wB.x, E[7], fmaf(wB.y, S[8], fmaf(wB.z, E[8], t5))));
            t6 = fmaf(wA.w, S[8], fmaf(wB.x, E[8], fmaf(wB.y, S[9], fmaf(wB.z, E[9], t6))));
            t7 = fmaf(wA.w, S[9], fmaf(wB.x, E[9], fmaf(wB.y, S[10], fmaf(wB.z, E[10], t7))));
            a0 += t0; a1 += t1; a2 += t2; a3 += t3;
            a4 += t4; a5 += t5; a6 += t6; a7 += t7;
        }
        acc[m][0] = a0; acc[m][1] = a1; acc[m][2] = a2; acc[m][3] = a3;
        acc[m][4] = a4; acc[m][5] = a5; acc[m][6] = a6; acc[m][7] = a7;

        // ---- S2: reduce x^2 parity sums over the 16-lane fill group ----
#pragma unroll
        for (int off = 1; off < 16; off <<= 1) {
            se2 += __shfl_xor_sync(FULL, se2, off);
            so2 += __shfl_xor_sync(FULL, so2, off);
        }
        if (j16 < 4) {
            // boundary samples of row rf: x0=pos[2], x1=pe[2], x509=pe[256],
            // x510=pos[257], x511=pe[257]
            float x0   = pos_[rf][2],  x1   = pe[rf][2];
            float x509 = pe[rf][256],  x510 = pos_[rf][257], x511 = pe[rf][257];
            float s2[7];
            s2[0] = so2 - x509 * x509 - x511 * x511;
            s2[1] = se2 - x510 * x510;
            s2[2] = so2 - x511 * x511;
            s2[3] = se2;
            s2[4] = so2;
            s2[5] = se2 - x0 * x0;
            s2[6] = so2 - x1 * x1;
            const float* wr = &ws[rf][j16][0];
            float c2 = 0.f;
#pragma unroll
            for (int w = 0; w < 7; w++) {
                float wv = wr[w];
                c2 = fmaf(wv * wv, s2[w], c2);
            }
            atomicAdd(&s_p2[j16], c2);
        }
        // ---- S1: sum of raw accumulators (the conv output IS sum w*x) ----
        {
            float s = ((a0 + a1) + (a2 + a3)) + ((a4 + a5) + (a6 + a7));
            s += __shfl_xor_sync(FULL, s, 4);
            s += __shfl_xor_sync(FULL, s, 8);
            s += __shfl_xor_sync(FULL, s, 16);
            if (lane < 4) atomicAdd(&s_p1[lane], s);
        }
        __syncthreads();   // smem (pe/pos/ws/s_p*) stable before next tile
    }

    // ---- publish block partials ----
    if (tid < 4) {
        g_part1[g * 4 + tid][b * 32 + fp] = s_p1[tid];
        g_part2[g * 4 + tid][b * 32 + fp] = s_p2[tid];
    }
    __threadfence();
    __syncthreads();

    // ---- grid barrier (epoch-versioned counter; graph-replay safe) ----
    if (tid == 0) {
        unsigned prev = atomicAdd(&g_count, 1u);
        if (prev == target - 1u) g_epoch = epoch + 1u;
        while (*(volatile unsigned*)&g_count < target) { __nanosleep(64); }
    }
    __syncthreads();
    __threadfence();

    // ---- phase 2: each warp finalizes one of the group's 4 channels ----
    {
        const int o = g * 4 + warp;
        float p1 = g_part1[o][lane] + g_part1[o][lane + 32];
        float p2 = g_part2[o][lane] + g_part2[o][lane + 32];
#pragma unroll
        for (int off = 16; off > 0; off >>= 1) {
            p1 += __shfl_xor_sync(FULL, p1, off);
            p2 += __shfl_xor_sync(FULL, p2, off);
        }
        if (lane == 0) {
            const float M = 1835008.f;   // B*D*E*t*W
            float mean = p1 / M;
            float var  = p2 / M - mean * mean;
            float a    = gamma[o] * rsqrtf(var + 1e-5f);
            s_ab[warp] = make_float2(a, 56.f * (beta[o] - mean * a));
        }
    }
    __syncthreads();

    // ---- phase 3: affine + LeakyReLU from registers, final store ----
    {
        const float2 ab = s_ab[oc];
#pragma unroll
        for (int m = 0; m < 2; m++) {
            const int fo = 2 * fp + m;
            float r0[8];
#pragma unroll
            for (int j = 0; j < 8; j++) {
                float v = fmaf(ab.x, acc[m][j], ab.y);
                r0[j] = (v >= 0.f) ? v : 0.01f * v;
            }
            int ob = ((b * Oo + g * 4 + oc) * FO + fo) * Tout + 8 * tc;
            *reinterpret_cast<float4*>(&out[ob])     = make_float4(r0[0], r0[1], r0[2], r0[3]);
            *reinterpret_cast<float4*>(&out[ob + 4]) = make_float4(r0[4], r0[5], r0[6], r0[7]);
        }
    }
}

extern "C" void kernel_launch(void* const* d_in, const int* in_sizes, int n_in,
                              void* d_out, int out_size) {
    const float* x     = (const float*)d_in[0];
    const float* wgt   = (const float*)d_in[1];
    const float* gamma = (const float*)d_in[2];
    const float* beta  = (const float*)d_in[3];

    fused_kernel<<<NBLK, 128>>>(x, wgt, gamma, beta, (float*)d_out);
}

// round 13
// speedup vs baseline: 1.1969x; 1.0122x over previous
#include <cuda_runtime.h>

// Problem constants
#define Bn   2
#define Cc   64
#define Oo   64
#define Gg   16
#define Ee   128
#define Tin  512
#define Wk   7
#define Dd   4
#define Tout 256
#define FO   64
#define PER  264   // padded de-interleaved row length (floats)

// BN-stat partials: [o][j], j = b*32 + d*8 + fh  (64 slots)
__device__ float  g_part1[Oo][64];
__device__ float  g_part2[Oo][64];
__device__ float2 g_ab[Oo];           // {a, bias56}

// ---------------------------------------------------------------------------
// Stats kernel (validated R8, 10.34us): grid (b,c,fh) = 1024 blocks, 256 thr.
// ---------------------------------------------------------------------------
__global__ __launch_bounds__(256) void stats_kernel(const float* __restrict__ x,
                                                    const float* __restrict__ wgt) {
    __shared__ float s_p1[4], s_p2[4];

    const int bid  = blockIdx.x;
    const int b    = bid >> 9;
    const int c    = (bid >> 3) & 63;
    const int fh   = bid & 7;
    const int tid  = threadIdx.x;
    const int warp = tid >> 5;
    const int lane = tid & 31;
    const int sl   = lane & 15;
    const int gidx = lane >> 4;
    const int f    = fh * 16 + warp * 2 + gidx;

    if (tid < 4) { s_p1[tid] = 0.f; s_p2[tid] = 0.f; }
    __syncthreads();

    const float4* row = reinterpret_cast<const float4*>(
        &x[((b * Cc + c) * Ee + f) * Tin]);

    float4 v[8];
#pragma unroll
    for (int k = 0; k < 8; k++) v[k] = row[sl + 16 * k];

    float se = 0.f, so = 0.f, se2 = 0.f, so2 = 0.f;
#pragma unroll
    for (int k = 0; k < 8; k++) {
        float4 q = v[k];
        se += q.x + q.z;  so += q.y + q.w;
        se2 = fmaf(q.x, q.x, se2); se2 = fmaf(q.z, q.z, se2);
        so2 = fmaf(q.y, q.y, so2); so2 = fmaf(q.w, q.w, so2);
    }

    const unsigned FULL = 0xffffffffu;
    const int base = lane & ~15;
    float x0   = __shfl_sync(FULL, v[0].x, base);
    float x1   = __shfl_sync(FULL, v[0].y, base);
    float x509 = __shfl_sync(FULL, v[7].y, base + 15);
    float x510 = __shfl_sync(FULL, v[7].z, base + 15);
    float x511 = __shfl_sync(FULL, v[7].w, base + 15);

#pragma unroll
    for (int off = 1; off < 16; off <<= 1) {
        se  += __shfl_xor_sync(FULL, se,  off);
        so  += __shfl_xor_sync(FULL, so,  off);
        se2 += __shfl_xor_sync(FULL, se2, off);
        so2 += __shfl_xor_sync(FULL, so2, off);
    }

    float c1 = 0.f, c2 = 0.f;
    if (sl < 4) {
        float s1[7], s2[7];
        s1[0] = so - x509 - x511;  s2[0] = so2 - x509 * x509 - x511 * x511;
        s1[1] = se - x510;         s2[1] = se2 - x510 * x510;
        s1[2] = so - x511;         s2[2] = so2 - x511 * x511;
        s1[3] = se;                s2[3] = se2;
        s1[4] = so;                s2[4] = so2;
        s1[5] = se - x0;           s2[5] = se2 - x0 * x0;
        s1[6] = so - x1;           s2[6] = so2 - x1 * x1;

        const int g = c >> 2, d = c & 3;
        const int o = g * 4 + sl;
        const float* wp = &wgt[((o * Dd + d) * Ee + f) * Wk];
#pragma unroll
        for (int w = 0; w < 7; w++) {
            float wv = wp[w];
            c1 = fmaf(wv, s1[w], c1);
            c2 = fmaf(wv * wv, s2[w], c2);
        }
    }
    c1 += __shfl_xor_sync(FULL, c1, 16);
    c2 += __shfl_xor_sync(FULL, c2, 16);
    if (lane < 4) {
        atomicAdd(&s_p1[lane], c1);
        atomicAdd(&s_p2[lane], c2);
    }
    __syncthreads();
    if (tid < 4) {
        const int g = c >> 2, d = c & 3;
        const int j = b * 32 + d * 8 + fh;
        g_part1[g * 4 + tid][j] = s_p1[tid];
        g_part2[g * 4 + tid][j] = s_p2[tid];
    }
}

// ---------------------------------------------------------------------------
// Finalize: 1 block, 64 threads. PDL: waits for stats completion, then reduces.
// ---------------------------------------------------------------------------
__global__ __launch_bounds__(64) void finalize_kernel(const float* __restrict__ gamma,
                                                      const float* __restrict__ beta) {
#if __CUDA_ARCH__ >= 900
    cudaGridDependencySynchronize();
#endif
    const int o = threadIdx.x;
    const float4* p1v = reinterpret_cast<const float4*>(g_part1[o]);
    const float4* p2v = reinterpret_cast<const float4*>(g_part2[o]);
    float p1 = 0.f, p2 = 0.f;
#pragma unroll
    for (int k = 0; k < 16; k++) {
        float4 a = p1v[k], b = p2v[k];
        p1 += (a.x + a.y) + (a.z + a.w);
        p2 += (b.x + b.y) + (b.z + b.w);
    }
    const float M = 1835008.f;   // B*D*E*t*W
    float mean = p1 / M;
    float var  = p2 / M - mean * mean;
    float a    = gamma[o] * rsqrtf(var + 1e-5f);
    g_ab[o] = make_float2(a, 56.f * (beta[o] - mean * a));
}

// ---------------------------------------------------------------------------
// Fused conv + BN-affine + LeakyReLU (validated R5/R6 core). Block = (b,g,fo),
// 2048 blocks, 128 threads. PDL: fill + FMA run BEFORE the dependency sync;
// g_ab is read only in the epilogue, after cudaGridDependencySynchronize().
// ---------------------------------------------------------------------------
__global__ __launch_bounds__(128) void conv_kernel(const float* __restrict__ x,
                                                   const float* __restrict__ wgt,
                                                   float* __restrict__ out) {
    __shared__ alignas(16) float pe[8][PER];
    __shared__ alignas(16) float pos_[8][PER];
    __shared__ alignas(16) float ws[8][4][8];   // [w0..w6, 0]

    const int bid  = blockIdx.x;
    const int b    = bid >> 10;
    const int g    = (bid >> 6) & 15;
    const int fo   = bid & 63;
    const int tid  = threadIdx.x;
    const int lane = tid & 31;
    const int warp = tid >> 5;
    const int oc   = lane & 3;
    const int tc   = warp * 8 + (lane >> 2);   // 0..31; outputs t = 8tc..8tc+7

    // zero boundary slots {0,1,258..263} of each pe/pos_ row
    {
        int r  = tid >> 4;
        int s  = tid & 15;
        int ss = s & 7;
        int idx = (ss < 2) ? ss : (256 + ss);
        if (s < 8) pe[r][idx] = 0.f; else pos_[r][idx] = 0.f;
    }

    // de-interleaving fill
#pragma unroll
    for (int k = 0; k < 8; k++) {
        const int c = g * 4 + (k & 3);
        const int f = 2 * fo + (k >> 2);
        float4 v = reinterpret_cast<const float4*>(
            &x[((b * Cc + c) * Ee + f) * Tin])[tid];
        *reinterpret_cast<float2*>(&pe[k][2 * tid + 2])   = make_float2(v.y, v.w);
        *reinterpret_cast<float2*>(&pos_[k][2 * tid + 2]) = make_float2(v.x, v.z);
    }

    // weights
#pragma unroll
    for (int m = 0; m < 2; m++) {
        int j  = tid + 128 * m;
        int r  = j >> 5;
        int o2 = (j >> 3) & 3;
        int w  = j & 7;
        int d  = r & 3;
        int f2 = r >> 2;
        ws[r][o2][w] = (w < 7)
            ? wgt[(((g * 4 + o2) * Dd + d) * Ee + (2 * fo + f2)) * Wk + w] : 0.f;
    }
    __syncthreads();

    float acc[8];
#pragma unroll
    for (int j = 0; j < 8; j++) acc[j] = 0.f;

#pragma unroll
    for (int r = 0; r < 8; r++) {
        const float4* pe4  = reinterpret_cast<const float4*>(pe[r]);
        const float4* pos4 = reinterpret_cast<const float4*>(pos_[r]);
        float E[12], S[12];
        *reinterpret_cast<float4*>(&E[0]) = pe4[2 * tc];
        *reinterpret_cast<float4*>(&E[4]) = pe4[2 * tc + 1];
        *reinterpret_cast<float4*>(&E[8]) = pe4[2 * tc + 2];
        *reinterpret_cast<float4*>(&S[0]) = pos4[2 * tc];
        *reinterpret_cast<float4*>(&S[4]) = pos4[2 * tc + 1];
        *reinterpret_cast<float4*>(&S[8]) = pos4[2 * tc + 2];
        float4 wA = *reinterpret_cast<const float4*>(&ws[r][oc][0]);
        float4 wB = *reinterpret_cast<const float4*>(&ws[r][oc][4]);
#pragma unroll
        for (int j = 0; j < 8; j++) {
            acc[j] = fmaf(wA.x, E[j],     acc[j]);
            acc[j] = fmaf(wA.y, S[j + 1], acc[j]);
            acc[j] = fmaf(wA.z, E[j + 1], acc[j]);
            acc[j] = fmaf(wA.w, S[j + 2], acc[j]);
            acc[j] = fmaf(wB.x, E[j + 2], acc[j]);
            acc[j] = fmaf(wB.y, S[j + 3], acc[j]);
            acc[j] = fmaf(wB.z, E[j + 3], acc[j]);
        }
    }

    // ---- PDL sync: BN coefficients become valid only after finalize ----
#if __CUDA_ARCH__ >= 900
    cudaGridDependencySynchronize();
#endif
    {
        const float2 ab = g_ab[g * 4 + oc];
        float r0[8];
#pragma unroll
        for (int j = 0; j < 8; j++) {
            float v = fmaf(ab.x, acc[j], ab.y);
            r0[j] = (v >= 0.f) ? v : 0.01f * v;
        }
        int ob = ((b * Oo + g * 4 + oc) * FO + fo) * Tout + 8 * tc;
        *reinterpret_cast<float4*>(&out[ob])     = make_float4(r0[0], r0[1], r0[2], r0[3]);
        *reinterpret_cast<float4*>(&out[ob + 4]) = make_float4(r0[4], r0[5], r0[6], r0[7]);
    }
}

extern "C" void kernel_launch(void* const* d_in, const int* in_sizes, int n_in,
                              void* d_out, int out_size) {
    const float* x     = (const float*)d_in[0];
    const float* wgt   = (const float*)d_in[1];
    const float* gamma = (const float*)d_in[2];
    const float* beta  = (const float*)d_in[3];
    float* out = (float*)d_out;

    // Primary: stats (plain launch)
    stats_kernel<<<1024, 256>>>(x, wgt);

    // Secondary launches with programmatic stream serialization (PDL):
    // they may begin before their predecessor completes; the device-side
    // cudaGridDependencySynchronize() provides the actual data ordering.
    cudaLaunchAttribute attr[1];
    attr[0].id = cudaLaunchAttributeProgrammaticStreamSerialization;
    attr[0].val.programmaticStreamSerializationAllowed = 1;

    {
        cudaLaunchConfig_t cfg = {};
        cfg.gridDim  = dim3(1, 1, 1);
        cfg.blockDim = dim3(64, 1, 1);
        cfg.dynamicSmemBytes = 0;
        cfg.stream = 0;
        cfg.attrs = attr;
        cfg.numAttrs = 1;
        cudaLaunchKernelEx(&cfg, finalize_kernel, gamma, beta);
    }
    {
        cudaLaunchConfig_t cfg = {};
        cfg.gridDim  = dim3(2048, 1, 1);
        cfg.blockDim = dim3(128, 1, 1);
        cfg.dynamicSmemBytes = 0;
        cfg.stream = 0;
        cfg.attrs = attr;
        cfg.numAttrs = 1;
        cudaLaunchKernelEx(&cfg, conv_kernel, x, wgt, out);
    }
}

// round 14
// speedup vs baseline: 1.3266x; 1.1083x over previous
#include <cuda_runtime.h>

// Problem constants
#define Bn   2
#define Cc   64
#define Oo   64
#define Gg   16
#define Ee   128
#define Tin  512
#define Wk   7
#define Dd   4
#define Tout 256
#define FO   64
#define PER  264   // padded de-interleaved row length (floats)

// BN-stat partials: [o][j], j = b*32 + d*8 + fh  (64 slots)
__device__ float  g_part1[Oo][64];
__device__ float  g_part2[Oo][64];
__device__ float2 g_ab[Oo];           // {a, bias56}

// ---------------------------------------------------------------------------
// Stats kernel (validated R8): grid (b,c,fh) = 1024 blocks, 256 threads.
// PDL: triggers launch-completion at entry so downstream grids co-schedule.
// ---------------------------------------------------------------------------
__global__ __launch_bounds__(256) void stats_kernel(const float* __restrict__ x,
                                                    const float* __restrict__ wgt) {
#if __CUDA_ARCH__ >= 900
    cudaTriggerProgrammaticLaunchCompletion();
#endif
    __shared__ float s_p1[4], s_p2[4];

    const int bid  = blockIdx.x;
    const int b    = bid >> 9;
    const int c    = (bid >> 3) & 63;
    const int fh   = bid & 7;
    const int tid  = threadIdx.x;
    const int warp = tid >> 5;
    const int lane = tid & 31;
    const int sl   = lane & 15;
    const int gidx = lane >> 4;
    const int f    = fh * 16 + warp * 2 + gidx;

    if (tid < 4) { s_p1[tid] = 0.f; s_p2[tid] = 0.f; }
    __syncthreads();

    const float4* row = reinterpret_cast<const float4*>(
        &x[((b * Cc + c) * Ee + f) * Tin]);

    float4 v[8];
#pragma unroll
    for (int k = 0; k < 8; k++) v[k] = row[sl + 16 * k];

    float se = 0.f, so = 0.f, se2 = 0.f, so2 = 0.f;
#pragma unroll
    for (int k = 0; k < 8; k++) {
        float4 q = v[k];
        se += q.x + q.z;  so += q.y + q.w;
        se2 = fmaf(q.x, q.x, se2); se2 = fmaf(q.z, q.z, se2);
        so2 = fmaf(q.y, q.y, so2); so2 = fmaf(q.w, q.w, so2);
    }

    const unsigned FULL = 0xffffffffu;
    const int base = lane & ~15;
    float x0   = __shfl_sync(FULL, v[0].x, base);
    float x1   = __shfl_sync(FULL, v[0].y, base);
    float x509 = __shfl_sync(FULL, v[7].y, base + 15);
    float x510 = __shfl_sync(FULL, v[7].z, base + 15);
    float x511 = __shfl_sync(FULL, v[7].w, base + 15);

#pragma unroll
    for (int off = 1; off < 16; off <<= 1) {
        se  += __shfl_xor_sync(FULL, se,  off);
        so  += __shfl_xor_sync(FULL, so,  off);
        se2 += __shfl_xor_sync(FULL, se2, off);
        so2 += __shfl_xor_sync(FULL, so2, off);
    }

    float c1 = 0.f, c2 = 0.f;
    if (sl < 4) {
        float s1[7], s2[7];
        s1[0] = so - x509 - x511;  s2[0] = so2 - x509 * x509 - x511 * x511;
        s1[1] = se - x510;         s2[1] = se2 - x510 * x510;
        s1[2] = so - x511;         s2[2] = so2 - x511 * x511;
        s1[3] = se;                s2[3] = se2;
        s1[4] = so;                s2[4] = so2;
        s1[5] = se - x0;           s2[5] = se2 - x0 * x0;
        s1[6] = so - x1;           s2[6] = so2 - x1 * x1;

        const int g = c >> 2, d = c & 3;
        const int o = g * 4 + sl;
        const float* wp = &wgt[((o * Dd + d) * Ee + f) * Wk];
#pragma unroll
        for (int w = 0; w < 7; w++) {
            float wv = wp[w];
            c1 = fmaf(wv, s1[w], c1);
            c2 = fmaf(wv * wv, s2[w], c2);
        }
    }
    c1 += __shfl_xor_sync(FULL, c1, 16);
    c2 += __shfl_xor_sync(FULL, c2, 16);
    if (lane < 4) {
        atomicAdd(&s_p1[lane], c1);
        atomicAdd(&s_p2[lane], c2);
    }
    __syncthreads();
    if (tid < 4) {
        const int g = c >> 2, d = c & 3;
        const int j = b * 32 + d * 8 + fh;
        g_part1[g * 4 + tid][j] = s_p1[tid];
        g_part2[g * 4 + tid][j] = s_p2[tid];
    }
}

// ---------------------------------------------------------------------------
// Finalize: 1 block, 64 threads. Triggers at entry (lets conv co-schedule),
// then waits for stats completion before reducing partials.
// ---------------------------------------------------------------------------
__global__ __launch_bounds__(64) void finalize_kernel(const float* __restrict__ gamma,
                                                      const float* __restrict__ beta) {
#if __CUDA_ARCH__ >= 900
    cudaTriggerProgrammaticLaunchCompletion();
    cudaGridDependencySynchronize();
#endif
    const int o = threadIdx.x;
    const float4* p1v = reinterpret_cast<const float4*>(g_part1[o]);
    const float4* p2v = reinterpret_cast<const float4*>(g_part2[o]);
    float p1 = 0.f, p2 = 0.f;
#pragma unroll
    for (int k = 0; k < 16; k++) {
        float4 a = p1v[k], b = p2v[k];
        p1 += (a.x + a.y) + (a.z + a.w);
        p2 += (b.x + b.y) + (b.z + b.w);
    }
    const float M = 1835008.f;   // B*D*E*t*W
    float mean = p1 / M;
    float var  = p2 / M - mean * mean;
    float a    = gamma[o] * rsqrtf(var + 1e-5f);
    g_ab[o] = make_float2(a, 56.f * (beta[o] - mean * a));
}

// ---------------------------------------------------------------------------
// Fused conv + BN-affine + LeakyReLU (validated R5/R6 core). Block = (b,g,fo),
// 2048 blocks, 128 threads. Fill + FMA run before the PDL dependency sync;
// g_ab is read only in the epilogue, after cudaGridDependencySynchronize().
// ---------------------------------------------------------------------------
__global__ __launch_bounds__(128) void conv_kernel(const float* __restrict__ x,
                                                   const float* __restrict__ wgt,
                                                   float* __restrict__ out) {
    __shared__ alignas(16) float pe[8][PER];
    __shared__ alignas(16) float pos_[8][PER];
    __shared__ alignas(16) float ws[8][4][8];   // [w0..w6, 0]

    const int bid  = blockIdx.x;
    const int b    = bid >> 10;
    const int g    = (bid >> 6) & 15;
    const int fo   = bid & 63;
    const int tid  = threadIdx.x;
    const int lane = tid & 31;
    const int warp = tid >> 5;
    const int oc   = lane & 3;
    const int tc   = warp * 8 + (lane >> 2);   // 0..31; outputs t = 8tc..8tc+7

    // zero boundary slots {0,1,258..263} of each pe/pos_ row
    {
        int r  = tid >> 4;
        int s  = tid & 15;
        int ss = s & 7;
        int idx = (ss < 2) ? ss : (256 + ss);
        if (s < 8) pe[r][idx] = 0.f; else pos_[r][idx] = 0.f;
    }

    // de-interleaving fill
#pragma unroll
    for (int k = 0; k < 8; k++) {
        const int c = g * 4 + (k & 3);
        const int f = 2 * fo + (k >> 2);
        float4 v = reinterpret_cast<const float4*>(
            &x[((b * Cc + c) * Ee + f) * Tin])[tid];
        *reinterpret_cast<float2*>(&pe[k][2 * tid + 2])   = make_float2(v.y, v.w);
        *reinterpret_cast<float2*>(&pos_[k][2 * tid + 2]) = make_float2(v.x, v.z);
    }

    // weights
#pragma unroll
    for (int m = 0; m < 2; m++) {
        int j  = tid + 128 * m;
        int r  = j >> 5;
        int o2 = (j >> 3) & 3;
        int w  = j & 7;
        int d  = r & 3;
        int f2 = r >> 2;
        ws[r][o2][w] = (w < 7)
            ? wgt[(((g * 4 + o2) * Dd + d) * Ee + (2 * fo + f2)) * Wk + w] : 0.f;
    }
    __syncthreads();

    float acc[8];
#pragma unroll
    for (int j = 0; j < 8; j++) acc[j] = 0.f;

#pragma unroll
    for (int r = 0; r < 8; r++) {
        const float4* pe4  = reinterpret_cast<const float4*>(pe[r]);
        const float4* pos4 = reinterpret_cast<const float4*>(pos_[r]);
        float E[12], S[12];
        *reinterpret_cast<float4*>(&E[0]) = pe4[2 * tc];
        *reinterpret_cast<float4*>(&E[4]) = pe4[2 * tc + 1];
        *reinterpret_cast<float4*>(&E[8]) = pe4[2 * tc + 2];
        *reinterpret_cast<float4*>(&S[0]) = pos4[2 * tc];
        *reinterpret_cast<float4*>(&S[4]) = pos4[2 * tc + 1];
        *reinterpret_cast<float4*>(&S[8]) = pos4[2 * tc + 2];
        float4 wA = *reinterpret_cast<const float4*>(&ws[r][oc][0]);
        float4 wB = *reinterpret_cast<const float4*>(&ws[r][oc][4]);
#pragma unroll
        for (int j = 0; j < 8; j++) {
            acc[j] = fmaf(wA.x, E[j],     acc[j]);
            acc[j] = fmaf(wA.y, S[j + 1], acc[j]);
            acc[j] = fmaf(wA.z, E[j + 1], acc[j]);
            acc[j] = fmaf(wA.w, S[j + 2], acc[j]);
            acc[j] = fmaf(wB.x, E[j + 2], acc[j]);
            acc[j] = fmaf(wB.y, S[j + 3], acc[j]);
            acc[j] = fmaf(wB.z, E[j + 3], acc[j]);
        }
    }

    // ---- PDL sync: BN coefficients become valid only after finalize ----
#if __CUDA_ARCH__ >= 900
    cudaGridDependencySynchronize();
#endif
    {
        const float2 ab = g_ab[g * 4 + oc];
        float r0[8];
#pragma unroll
        for (int j = 0; j < 8; j++) {
            float v = fmaf(ab.x, acc[j], ab.y);
            r0[j] = (v >= 0.f) ? v : 0.01f * v;
        }
        int ob = ((b * Oo + g * 4 + oc) * FO + fo) * Tout + 8 * tc;
        *reinterpret_cast<float4*>(&out[ob])     = make_float4(r0[0], r0[1], r0[2], r0[3]);
        *reinterpret_cast<float4*>(&out[ob + 4]) = make_float4(r0[4], r0[5], r0[6], r0[7]);
    }
}

extern "C" void kernel_launch(void* const* d_in, const int* in_sizes, int n_in,
                              void* d_out, int out_size) {
    const float* x     = (const float*)d_in[0];
    const float* wgt   = (const float*)d_in[1];
    const float* gamma = (const float*)d_in[2];
    const float* beta  = (const float*)d_in[3];
    float* out = (float*)d_out;

    // Primary: stats (plain launch; triggers early on-device)
    stats_kernel<<<1024, 256>>>(x, wgt);

    // Secondary launches with programmatic stream serialization (PDL).
    cudaLaunchAttribute attr[1];
    attr[0].id = cudaLaunchAttributeProgrammaticStreamSerialization;
    attr[0].val.programmaticStreamSerializationAllowed = 1;

    {
        cudaLaunchConfig_t cfg = {};
        cfg.gridDim  = dim3(1, 1, 1);
        cfg.blockDim = dim3(64, 1, 1);
        cfg.dynamicSmemBytes = 0;
        cfg.stream = 0;
        cfg.attrs = attr;
        cfg.numAttrs = 1;
        cudaLaunchKernelEx(&cfg, finalize_kernel, gamma, beta);
    }
    {
        cudaLaunchConfig_t cfg = {};
        cfg.gridDim  = dim3(2048, 1, 1);
        cfg.blockDim = dim3(128, 1, 1);
        cfg.dynamicSmemBytes = 0;
        cfg.stream = 0;
        cfg.attrs = attr;
        cfg.numAttrs = 1;
        cudaLaunchKernelEx(&cfg, conv_kernel, x, wgt, out);
    }
}